// round 16
// baseline (speedup 1.0000x reference)
#include <cuda_runtime.h>
#include <cuda_fp16.h>
#include <math.h>
#include <stdint.h>

#define NPIX 16384
constexpr int NT = 512;
constexpr float QS = 0.72134752044448170f;  // 0.5 * log2(e)

__device__ float g_te[8 * 1024];
__device__ float g_film[8 * 128];
__device__ __half g_wt[13 * 4608];
__device__ float g_qb2[64];
__device__ float g_fc1b2[256];

__device__ __forceinline__ uint32_t s2u32(const void* p) {
    uint32_t a;
    asm("{ .reg .u64 t; cvta.to.shared.u64 t, %1; cvt.u32.u64 %0, t; }" : "=r"(a) : "l"(p));
    return a;
}
__device__ __forceinline__ uint32_t expp(float a, float b) {
    half2 h = __floats2half2_rn(a, b);
    uint32_t r;
    asm("ex2.approx.f16x2 %0, %1;" : "=r"(r) : "r"(*(uint32_t*)&h));
    return r;
}
__device__ __forceinline__ half2 u2h(uint32_t u) { return *(half2*)&u; }
__device__ __forceinline__ float geluf(float v) {
    return 0.5f * v * (1.f + erff(v * 0.70710678118654752f));
}

#define LDSM4(r0, r1, r2, r3, addr)                                             \
    asm volatile("ldmatrix.sync.aligned.m8n8.x4.shared.b16 {%0,%1,%2,%3}, [%4];" \
                 : "=r"(r0), "=r"(r1), "=r"(r2), "=r"(r3) : "r"(addr))
#define LDSM2(r0, r1, addr)                                                      \
    asm volatile("ldmatrix.sync.aligned.m8n8.x2.shared.b16 {%0,%1}, [%2];"       \
                 : "=r"(r0), "=r"(r1) : "r"(addr))
#define MMA16(d, a0, a1, a2, a3, b0, b1)                                         \
    asm volatile("mma.sync.aligned.m16n8k16.row.col.f32.f16.f16.f32 "            \
                 "{%0,%1,%2,%3}, {%4,%5,%6,%7}, {%8,%9}, {%0,%1,%2,%3};"         \
                 : "+f"(d[0]), "+f"(d[1]), "+f"(d[2]), "+f"(d[3])                \
                 : "r"(a0), "r"(a1), "r"(a2), "r"(a3), "r"(b0), "r"(b1))
#define MMA8(d, a0, a1, b0)                                                      \
    asm volatile("mma.sync.aligned.m16n8k8.row.col.f32.f16.f16.f32 "             \
                 "{%0,%1,%2,%3}, {%4,%5}, {%6}, {%0,%1,%2,%3};"                  \
                 : "+f"(d[0]), "+f"(d[1]), "+f"(d[2]), "+f"(d[3])                \
                 : "r"(a0), "r"(a1), "r"(b0))
#define CPCOMMIT asm volatile("cp.async.commit_group;" ::: "memory")
#define CPWAIT   asm volatile("cp.async.wait_group 0;" ::: "memory")

__device__ __forceinline__ void copy_w(uint32_t dst, const __half* __restrict__ src,
                                       int tid) {
    #pragma unroll
    for (int i = tid; i < 576; i += NT)
        asm volatile("cp.async.cg.shared.global [%0], [%1], 16;"
                     :: "r"(dst + 16u * (uint32_t)i), "l"(src + 8 * i) : "memory");
}

__device__ __forceinline__ void gemmF16(uint32_t aB, uint32_t bB, int tt, int cc,
                                        int lane, float acc[4][4]) {
    int ar = tt + (lane & 7) + 8 * ((lane >> 3) & 1), ak = 8 * (lane >> 4);
    int br = cc + (lane & 7) + 8 * (lane >> 4), bk = 8 * ((lane >> 3) & 1);
    uint32_t aA = aB + (uint32_t)((ar * 72 + ak) * 2);
    uint32_t bA0 = bB + (uint32_t)((br * 72 + bk) * 2);
    uint32_t bA1 = bA0 + 16 * 144;
    #pragma unroll
    for (int ks = 0; ks < 4; ks++) {
        uint32_t a0, a1, a2, a3, b0, b1, b2, b3;
        LDSM4(a0, a1, a2, a3, aA + 32 * ks);
        LDSM4(b0, b1, b2, b3, bA0 + 32 * ks);
        MMA16(acc[0], a0, a1, a2, a3, b0, b1);
        MMA16(acc[1], a0, a1, a2, a3, b2, b3);
        LDSM4(b0, b1, b2, b3, bA1 + 32 * ks);
        MMA16(acc[2], a0, a1, a2, a3, b0, b1);
        MMA16(acc[3], a0, a1, a2, a3, b2, b3);
    }
}

// ---------------------------------------------------------------------------
// Merged precursor: blocks [0,2048) = pool (float4, shfl-reduce),
// blocks [2048,2061) = weight prep (hidden under the memory-bound pool).
// ---------------------------------------------------------------------------
__global__ void __launch_bounds__(256) pre_kernel(
    const float* __restrict__ te,
    const float* __restrict__ qw, const float* __restrict__ kw,
    const float* __restrict__ vw, const float* __restrict__ ow,
    const float* __restrict__ fc1w, const float* __restrict__ fc2w,
    const float* __restrict__ cw,
    const float* __restrict__ ln1w, const float* __restrict__ ln1b,
    const float* __restrict__ ln2w, const float* __restrict__ ln2b,
    const float* __restrict__ qb, const float* __restrict__ fc1b) {
    const int tid = threadIdx.x;
    if (blockIdx.x < 2048) {
        // pool: block = (b, c, ic); thread = cols (lane&31)*4, rows (w*4..w*4+3)
        __shared__ float sw[32];  // [warp][jc]
        const int lane = tid & 31, w = tid >> 5;
        const int ic = blockIdx.x & 3, c = (blockIdx.x >> 2) & 63, b = blockIdx.x >> 8;
        const float* src = te + ((size_t)(b * 64 + c)) * NPIX +
                           (size_t)(ic * 32 + w * 4) * 128 + lane * 4;
        float4 v0 = *reinterpret_cast<const float4*>(src);
        float4 v1 = *reinterpret_cast<const float4*>(src + 128);
        float4 v2 = *reinterpret_cast<const float4*>(src + 256);
        float4 v3 = *reinterpret_cast<const float4*>(src + 384);
        float s = (v0.x + v0.y + v0.z + v0.w) + (v1.x + v1.y + v1.z + v1.w) +
                  (v2.x + v2.y + v2.z + v2.w) + (v3.x + v3.y + v3.z + v3.w);
        s += __shfl_xor_sync(~0u, s, 1);
        s += __shfl_xor_sync(~0u, s, 2);
        s += __shfl_xor_sync(~0u, s, 4);
        if ((lane & 7) == 0) sw[w * 4 + (lane >> 3)] = s;
        __syncthreads();
        if (tid < 4) {
            float tsum = 0.f;
            #pragma unroll
            for (int ww = 0; ww < 8; ww++) tsum += sw[ww * 4 + tid];
            g_te[b * 1024 + c * 16 + ic * 4 + tid] = tsum * (1.0f / 1024.0f);
        }
        return;
    }
    // prep: convert/transpose weights; fold LN affines + QS; parallel bias folds
    const int slot = blockIdx.x - 2048;
    __half* dst = g_wt + slot * 4608;
    for (int i = tid; i < 4608; i += 256) {
        int o = i / 72, k = i % 72;
        float v = 0.f;
        if (k < 64) {
            if (slot == 0) v = qw[k * 64 + o] * ln1w[k] * QS;
            else if (slot == 1) v = kw[k * 64 + o];
            else if (slot == 2) v = vw[k * 64 + o];
            else if (slot == 3) v = ow[k * 64 + o];
            else if (slot < 8) v = fc1w[k * 256 + (slot - 4) * 64 + o] * ln2w[k];
            else if (slot < 12) v = fc2w[(slot - 8) * 4096 + k * 64 + o];
            else v = cw[o * 64 + k];
        }
        dst[i] = __float2half(v);
    }
    if (slot == 0) {
        int j = tid >> 2, part = tid & 3;
        float s = 0.f;
        #pragma unroll
        for (int k = 16 * part; k < 16 * part + 16; k++)
            s = fmaf(ln1b[k], qw[k * 64 + j], s);
        s += __shfl_xor_sync(~0u, s, 1);
        s += __shfl_xor_sync(~0u, s, 2);
        if (part == 0) g_qb2[j] = (s + qb[j]) * QS;
    } else if (slot >= 4 && slot < 8) {
        int j = (slot - 4) * 64 + (tid >> 2), part = tid & 3;
        float s = 0.f;
        #pragma unroll
        for (int k = 16 * part; k < 16 * part + 16; k++)
            s = fmaf(ln2b[k], fc1w[k * 256 + j], s);
        s += __shfl_xor_sync(~0u, s, 1);
        s += __shfl_xor_sync(~0u, s, 2);
        if (part == 0) g_fc1b2[j] = s + fc1b[j];
    }
}

// film: 512 threads, 4 partials per output
__global__ void __launch_bounds__(512) film_kernel(
    const float* __restrict__ m1w, const float* __restrict__ m1b,
    const float* __restrict__ m2w, const float* __restrict__ m2b) {
    __shared__ float ste[1024];
    __shared__ float red[512];
    __shared__ float shm[128];
    const int b = blockIdx.x, tid = threadIdx.x;
    const int j = tid & 127, p = tid >> 7;
    for (int i = tid; i < 1024; i += 512) ste[i] = g_te[b * 1024 + i];
    __syncthreads();
    float a = 0.f;
    #pragma unroll 4
    for (int k = 256 * p; k < 256 * p + 256; k++)
        a = fmaf(ste[k], m1w[k * 128 + j], a);
    red[tid] = a;
    __syncthreads();
    if (tid < 128) {
        float acc = red[tid] + red[tid + 128] + red[tid + 256] + red[tid + 384] + m1b[tid];
        shm[tid] = acc > 0.f ? acc : 0.01f * acc;
    }
    __syncthreads();
    float c = 0.f;
    #pragma unroll 4
    for (int k = 32 * p; k < 32 * p + 32; k++)
        c = fmaf(shm[k], m2w[k * 128 + j], c);
    red[tid] = c;
    __syncthreads();
    if (tid < 128)
        g_film[b * 128 + tid] =
            red[tid] + red[tid + 128] + red[tid + 256] + red[tid + 384] + m2b[tid];
}

// half offsets
constexpr int H_H = 0, H_ACT = 9216, H_XQ = 18432, H_KS = 27648, H_VC = 44032;
constexpr int H_F = 52736;
constexpr int SMEM_BYTES = (52736 + 768) * 2;  // 107008

__device__ __forceinline__ void stage_act(__half* dst, const float* __restrict__ g, int tid) {
    #pragma unroll
    for (int i = tid; i < 4096; i += NT) {
        int tok = i & 127, c = (i >> 7) << 1;
        *reinterpret_cast<half2*>(dst + tok * 72 + c) =
            __floats2half2_rn(g[(size_t)c * NPIX + tok], g[(size_t)(c + 1) * NPIX + tok]);
    }
}

__global__ void __launch_bounds__(NT, 2) fused_kernel(
    const float* __restrict__ x, const float* __restrict__ te,
    const float* __restrict__ kb, const float* __restrict__ vb,
    const float* __restrict__ ob, const float* __restrict__ fc2b,
    const float* __restrict__ cb, float* __restrict__ out) {
    extern __shared__ __align__(16) __half sh[];
    float* fm = reinterpret_cast<float*>(sh + H_F);
    const int tid = threadIdx.x;
    const int w = tid >> 5, lane = tid & 31;
    const int g = lane >> 2, t = lane & 3;
    const int tt = 16 * (w & 3), cc = 32 * (w >> 2);
    const int b = blockIdx.x >> 7, row = blockIdx.x & 127;
    const size_t base = (size_t)b * 64 * NPIX + (size_t)row * 128;
    const uint32_t ub = s2u32(sh);
    const int o0 = tt + g, o1 = o0 + 8;

    // A: async weight copies + x/prior staging + film
    copy_w(ub + H_KS * 2, g_wt + 1 * 4608, tid);            // kw
    copy_w(ub + (H_KS + 4608) * 2, g_wt + 2 * 4608, tid);   // vw
    copy_w(ub + H_VC * 2, g_wt + 0 * 4608, tid);            // qw'
    CPCOMMIT;
    stage_act(sh + H_XQ, x + base, tid);
    stage_act(sh + H_H, te + base, tid);
    if (tid < 64) {
        fm[256 + tid] = g_film[b * 128 + tid];
        fm[320 + tid] = g_film[b * 128 + 64 + tid];
    }
    CPWAIT;
    __syncthreads();

    // B: LN1 stats
    {
        int tok = tid >> 2, p = tid & 3;
        const half2* rp = reinterpret_cast<const half2*>(sh + H_H + tok * 72 + p * 16);
        float sum = 0.f, sq = 0.f;
        #pragma unroll
        for (int m = 0; m < 8; m++) {
            float2 v = __half22float2(rp[m]);
            sum += v.x + v.y; sq += v.x * v.x + v.y * v.y;
        }
        sum += __shfl_xor_sync(~0u, sum, 1); sum += __shfl_xor_sync(~0u, sum, 2);
        sq += __shfl_xor_sync(~0u, sq, 1); sq += __shfl_xor_sync(~0u, sq, 2);
        if (p == 0) {
            float mu = sum * (1.f / 64.f);
            fm[tok] = mu;
            fm[128 + tok] = rsqrtf(fmaxf(sq * (1.f / 64.f) - mu * mu, 0.f) + 1e-5f);
        }
    }
    __syncthreads();
    // normalize z only (LN affine folded into qw')
    #pragma unroll
    for (int i = tid; i < 4096; i += NT) {
        int tok = i & 127, c = (i >> 7) << 1;
        float2 v = __half22float2(*reinterpret_cast<half2*>(sh + H_H + tok * 72 + c));
        float mu = fm[tok], rs = fm[128 + tok];
        *reinterpret_cast<half2*>(sh + H_ACT + tok * 72 + c) =
            __floats2half2_rn((v.x - mu) * rs, (v.y - mu) * rs);
    }
    __syncthreads();

    // C1: K,V GEMMs
    float aK[4][4] = {}, aV[4][4] = {};
    gemmF16(ub + H_KS * 2, ub + H_XQ * 2, tt, cc, lane, aK);
    gemmF16(ub + (H_KS + 4608) * 2, ub + H_XQ * 2, tt, cc, lane, aV);
    __syncthreads();
    // zero KS
    #pragma unroll
    for (int i = tid; i < 2048; i += NT)
        reinterpret_cast<uint4*>(sh + H_KS)[i] = make_uint4(0, 0, 0, 0);
    __syncthreads();
    // C2: K epilogue -> K_s; Q GEMM
    {
        int h0 = o0 >> 2, s0 = 4 * (h0 & 1) + (o0 & 3);
        int h1 = o1 >> 2, s1 = 4 * (h1 & 1) + (o1 & 3);
        float kb0 = kb[o0], kb1 = kb[o1];
        #pragma unroll
        for (int j = 0; j < 4; j++) {
            int tok = cc + 8 * j + 2 * t;
            sh[H_KS + h0 * 1024 + tok * 8 + s0] = __float2half(aK[j][0] + kb0);
            sh[H_KS + h0 * 1024 + (tok + 1) * 8 + s0] = __float2half(aK[j][1] + kb0);
            sh[H_KS + h1 * 1024 + tok * 8 + s1] = __float2half(aK[j][2] + kb1);
            sh[H_KS + h1 * 1024 + (tok + 1) * 8 + s1] = __float2half(aK[j][3] + kb1);
        }
    }
    float aQ[4][4] = {};
    gemmF16(ub + H_VC * 2, ub + H_ACT * 2, tt, cc, lane, aQ);
    __syncthreads();
    // C3: V -> VC channel-major; Q (pre-scaled) -> XQ token-major
    {
        float vb0 = vb[o0], vb1 = vb[o1];
        float qb0 = g_qb2[o0], qb1 = g_qb2[o1];
        #pragma unroll
        for (int j = 0; j < 4; j++) {
            int tok = cc + 8 * j + 2 * t;
            *reinterpret_cast<half2*>(sh + H_VC + o0 * 136 + tok) =
                __floats2half2_rn(aV[j][0] + vb0, aV[j][1] + vb0);
            *reinterpret_cast<half2*>(sh + H_VC + o1 * 136 + tok) =
                __floats2half2_rn(aV[j][2] + vb1, aV[j][3] + vb1);
            sh[H_XQ + tok * 72 + o0] = __float2half(aQ[j][0] + qb0);
            sh[H_XQ + (tok + 1) * 72 + o0] = __float2half(aQ[j][1] + qb0);
            sh[H_XQ + tok * 72 + o1] = __float2half(aQ[j][2] + qb1);
            sh[H_XQ + (tok + 1) * 72 + o1] = __float2half(aQ[j][3] + qb1);
        }
    }
    __syncthreads();

    // D: MMA attention — warp = head w; ow copy overlapped with mainloop
    {
        const int h = w, p8 = (h >> 1) * 8;
        uint32_t kb_[16];
        uint32_t ksb = ub + (uint32_t)(H_KS + h * 1024) * 2 + (uint32_t)((lane & 15) * 16);
        #pragma unroll
        for (int jj = 0; jj < 8; jj++) LDSM2(kb_[2 * jj], kb_[2 * jj + 1], ksb + 256 * jj);
        __syncthreads();  // all K_s reads done
        copy_w(ub + H_KS * 2, g_wt + 3 * 4608, tid);  // ow (overlaps loop below)
        CPCOMMIT;
        const uint32_t qbase = ub + (uint32_t)H_XQ * 2 + (uint32_t)(((lane & 15) * 72 + p8) * 2);
        const uint32_t vbase = ub + (uint32_t)(H_VC + (4 * h + (lane & 7)) * 136 +
                                               8 * ((lane >> 3) & 1)) * 2;
        #pragma unroll
        for (int qt = 0; qt < 8; qt++) {
            uint32_t a0, a1;
            LDSM2(a0, a1, qbase + qt * (16 * 144));
            float pv[4] = {0.f, 0.f, 0.f, 0.f};
            half2 lg = __float2half2_rn(0.f), lh = __float2half2_rn(0.f);
            float lfg = 0.f, lfh = 0.f;
            #pragma unroll
            for (int j = 0; j < 8; j++) {
                float c[4] = {0.f, 0.f, 0.f, 0.f}, d[4] = {0.f, 0.f, 0.f, 0.f};
                MMA8(c, a0, a1, kb_[2 * j]);
                MMA8(d, a0, a1, kb_[2 * j + 1]);
                uint32_t e0 = expp(c[0], c[1]), e1 = expp(c[2], c[3]);
                uint32_t e2 = expp(d[0], d[1]), e3 = expp(d[2], d[3]);
                lg = __hadd2(lg, __hadd2(u2h(e0), u2h(e2)));
                lh = __hadd2(lh, __hadd2(u2h(e1), u2h(e3)));
                uint32_t vb0, vb1;
                LDSM2(vb0, vb1, vbase + 32 * j);
                MMA16(pv, e0, e1, e2, e3, vb0, vb1);
                if ((j & 3) == 3) {
                    float2 f = __half22float2(lg); lfg += f.x + f.y;
                    f = __half22float2(lh); lfh += f.x + f.y;
                    lg = __float2half2_rn(0.f); lh = __float2half2_rn(0.f);
                }
            }
            lfg += __shfl_xor_sync(~0u, lfg, 1); lfg += __shfl_xor_sync(~0u, lfg, 2);
            lfh += __shfl_xor_sync(~0u, lfh, 1); lfh += __shfl_xor_sync(~0u, lfh, 2);
            float ig = __fdividef(1.f, lfg), ih = __fdividef(1.f, lfh);
            if (t < 2) {
                int tokg = 16 * qt + g;
                *reinterpret_cast<half2*>(sh + H_ACT + tokg * 72 + 4 * h + 2 * t) =
                    __floats2half2_rn(pv[0] * ig, pv[1] * ig);
                *reinterpret_cast<half2*>(sh + H_ACT + (tokg + 8) * 72 + 4 * h + 2 * t) =
                    __floats2half2_rn(pv[2] * ih, pv[3] * ih);
            }
        }
    }
    CPWAIT;
    __syncthreads();

    // E: O GEMM, h = acc + ob + prior (RMW H)
    {
        float aO[4][4] = {};
        gemmF16(ub + H_KS * 2, ub + H_ACT * 2, tt, cc, lane, aO);
        float b0 = ob[o0], b1 = ob[o1];
        #pragma unroll
        for (int j = 0; j < 4; j++) {
            int tok = cc + 8 * j + 2 * t;
            #pragma unroll
            for (int d = 0; d < 4; d++) {
                int idx = H_H + (tok + (d & 1)) * 72 + ((d < 2) ? o0 : o1);
                sh[idx] = __float2half(aO[j][d] + ((d < 2) ? b0 : b1) + __half2float(sh[idx]));
            }
        }
    }
    __syncthreads();
    // LN2 stats + async copies (fc1'_0, fc2_0, cw)
    {
        int tok = tid >> 2, p = tid & 3;
        const half2* rp = reinterpret_cast<const half2*>(sh + H_H + tok * 72 + p * 16);
        float sum = 0.f, sq = 0.f;
        #pragma unroll
        for (int m = 0; m < 8; m++) {
            float2 v = __half22float2(rp[m]);
            sum += v.x + v.y; sq += v.x * v.x + v.y * v.y;
        }
        sum += __shfl_xor_sync(~0u, sum, 1); sum += __shfl_xor_sync(~0u, sum, 2);
        sq += __shfl_xor_sync(~0u, sq, 1); sq += __shfl_xor_sync(~0u, sq, 2);
        if (p == 0) {
            float mu = sum * (1.f / 64.f);
            fm[tok] = mu;
            fm[128 + tok] = rsqrtf(fmaxf(sq * (1.f / 64.f) - mu * mu, 0.f) + 1e-5f);
        }
    }
    copy_w(ub + (H_KS + 4608) * 2, g_wt + 4 * 4608, tid);
    copy_w(ub + (H_KS + 9216) * 2, g_wt + 8 * 4608, tid);
    copy_w(ub + H_KS * 2, g_wt + 12 * 4608, tid);
    CPCOMMIT;
    __syncthreads();
    // normalize z only (affine folded into fc1w')
    #pragma unroll
    for (int i = tid; i < 4096; i += NT) {
        int tok = i & 127, c = (i >> 7) << 1;
        float2 v = __half22float2(*reinterpret_cast<half2*>(sh + H_H + tok * 72 + c));
        float mu = fm[tok], rs = fm[128 + tok];
        *reinterpret_cast<half2*>(sh + H_ACT + tok * 72 + c) =
            __floats2half2_rn((v.x - mu) * rs, (v.y - mu) * rs);
    }
    CPWAIT;
    __syncthreads();

    // F: FFN (double-buffered)
    float aF2[4][4] = {};
    for (int jb = 0; jb < 4; jb++) {
        float aF1[4][4] = {};
        gemmF16(ub + (H_KS + 4608) * 2, ub + H_ACT * 2, tt, cc, lane, aF1);
        __syncthreads();
        {
            float b0 = g_fc1b2[jb * 64 + o0], b1 = g_fc1b2[jb * 64 + o1];
            #pragma unroll
            for (int j = 0; j < 4; j++) {
                int tok = cc + 8 * j + 2 * t;
                sh[H_XQ + tok * 72 + o0] = __float2half(geluf(aF1[j][0] + b0));
                sh[H_XQ + (tok + 1) * 72 + o0] = __float2half(geluf(aF1[j][1] + b0));
                sh[H_XQ + tok * 72 + o1] = __float2half(geluf(aF1[j][2] + b1));
                sh[H_XQ + (tok + 1) * 72 + o1] = __float2half(geluf(aF1[j][3] + b1));
            }
        }
        if (jb < 3) {
            copy_w(ub + (H_KS + 4608) * 2, g_wt + (5 + jb) * 4608, tid);
            CPCOMMIT;
        }
        CPWAIT;
        __syncthreads();
        gemmF16(ub + (H_KS + 9216) * 2, ub + H_XQ * 2, tt, cc, lane, aF2);
        __syncthreads();
        if (jb < 3) {
            copy_w(ub + (H_KS + 9216) * 2, g_wt + (9 + jb) * 4608, tid);
            CPCOMMIT;
        }
    }
    // G: hfin -> ACT (cw already staged at KS+0)
    {
        float b0 = fc2b[o0], b1 = fc2b[o1];
        #pragma unroll
        for (int j = 0; j < 4; j++) {
            int tok = cc + 8 * j + 2 * t;
            #pragma unroll
            for (int d = 0; d < 4; d++) {
                int tk = tok + (d & 1), o = (d < 2) ? o0 : o1;
                sh[H_ACT + tk * 72 + o] = __float2half(
                    aF2[j][d] + ((d < 2) ? b0 : b1) + __half2float(sh[H_H + tk * 72 + o]));
            }
        }
    }
    CPWAIT;
    __syncthreads();

    // H: conv GEMM + cb + x + FiLM -> out
    {
        float aC[4][4] = {};
        gemmF16(ub + H_KS * 2, ub + H_ACT * 2, tt, cc, lane, aC);
        float cb0 = cb[o0], cb1 = cb[o1];
        float g0 = fm[256 + o0], g1 = fm[256 + o1];
        float bt0 = fm[320 + o0], bt1 = fm[320 + o1];
        #pragma unroll
        for (int j = 0; j < 4; j++) {
            int tok = cc + 8 * j + 2 * t;
            float2 x0 = *reinterpret_cast<const float2*>(&x[base + (size_t)o0 * NPIX + tok]);
            float2 x1 = *reinterpret_cast<const float2*>(&x[base + (size_t)o1 * NPIX + tok]);
            float v; float2 r0, r1;
            v = aC[j][0] + cb0 + x0.x; r0.x = v + g0 * v + bt0;
            v = aC[j][1] + cb0 + x0.y; r0.y = v + g0 * v + bt0;
            v = aC[j][2] + cb1 + x1.x; r1.x = v + g1 * v + bt1;
            v = aC[j][3] + cb1 + x1.y; r1.y = v + g1 * v + bt1;
            *reinterpret_cast<float2*>(&out[base + (size_t)o0 * NPIX + tok]) = r0;
            *reinterpret_cast<float2*>(&out[base + (size_t)o1 * NPIX + tok]) = r1;
        }
    }
}

extern "C" void kernel_launch(void* const* d_in, const int* in_sizes, int n_in,
                              void* d_out, int out_size) {
    const float* x = (const float*)d_in[0];
    const float* te = (const float*)d_in[1];
    cudaFuncSetAttribute(fused_kernel, cudaFuncAttributeMaxDynamicSharedMemorySize,
                         SMEM_BYTES);
    pre_kernel<<<2061, 256>>>(te, (const float*)d_in[2], (const float*)d_in[4],
                              (const float*)d_in[6], (const float*)d_in[8],
                              (const float*)d_in[14], (const float*)d_in[16],
                              (const float*)d_in[18], (const float*)d_in[10],
                              (const float*)d_in[11], (const float*)d_in[12],
                              (const float*)d_in[13], (const float*)d_in[3],
                              (const float*)d_in[15]);
    film_kernel<<<8, 512>>>((const float*)d_in[20], (const float*)d_in[21],
                            (const float*)d_in[22], (const float*)d_in[23]);
    fused_kernel<<<1024, NT, SMEM_BYTES>>>(
        x, te, (const float*)d_in[5], (const float*)d_in[7], (const float*)d_in[9],
        (const float*)d_in[17], (const float*)d_in[19], (float*)d_out);
}

// round 17
// speedup vs baseline: 1.0196x; 1.0196x over previous
#include <cuda_runtime.h>
#include <cuda_fp16.h>
#include <math.h>
#include <stdint.h>

#define NPIX 16384
constexpr int NT = 512;
constexpr float QS = 0.72134752044448170f;  // 0.5 * log2(e)

__device__ float g_te[8 * 1024];
__device__ float g_film[8 * 128];
__device__ __half g_wt[13 * 4608];
__device__ float g_qb2[64];
__device__ float g_fc1b2[256];

__device__ __forceinline__ uint32_t s2u32(const void* p) {
    uint32_t a;
    asm("{ .reg .u64 t; cvta.to.shared.u64 t, %1; cvt.u32.u64 %0, t; }" : "=r"(a) : "l"(p));
    return a;
}
__device__ __forceinline__ uint32_t expp(float a, float b) {
    half2 h = __floats2half2_rn(a, b);
    uint32_t r;
    asm("ex2.approx.f16x2 %0, %1;" : "=r"(r) : "r"(*(uint32_t*)&h));
    return r;
}
__device__ __forceinline__ half2 u2h(uint32_t u) { return *(half2*)&u; }
__device__ __forceinline__ float geluf(float v) {
    return 0.5f * v * (1.f + erff(v * 0.70710678118654752f));
}

#define LDSM4(r0, r1, r2, r3, addr)                                             \
    asm volatile("ldmatrix.sync.aligned.m8n8.x4.shared.b16 {%0,%1,%2,%3}, [%4];" \
                 : "=r"(r0), "=r"(r1), "=r"(r2), "=r"(r3) : "r"(addr))
#define LDSM2(r0, r1, addr)                                                      \
    asm volatile("ldmatrix.sync.aligned.m8n8.x2.shared.b16 {%0,%1}, [%2];"       \
                 : "=r"(r0), "=r"(r1) : "r"(addr))
#define MMA16(d, a0, a1, a2, a3, b0, b1)                                         \
    asm volatile("mma.sync.aligned.m16n8k16.row.col.f32.f16.f16.f32 "            \
                 "{%0,%1,%2,%3}, {%4,%5,%6,%7}, {%8,%9}, {%0,%1,%2,%3};"         \
                 : "+f"(d[0]), "+f"(d[1]), "+f"(d[2]), "+f"(d[3])                \
                 : "r"(a0), "r"(a1), "r"(a2), "r"(a3), "r"(b0), "r"(b1))
#define MMA8(d, a0, a1, b0)                                                      \
    asm volatile("mma.sync.aligned.m16n8k8.row.col.f32.f16.f16.f32 "             \
                 "{%0,%1,%2,%3}, {%4,%5}, {%6}, {%0,%1,%2,%3};"                  \
                 : "+f"(d[0]), "+f"(d[1]), "+f"(d[2]), "+f"(d[3])                \
                 : "r"(a0), "r"(a1), "r"(b0))
#define CPCOMMIT asm volatile("cp.async.commit_group;" ::: "memory")
#define CPWAIT   asm volatile("cp.async.wait_group 0;" ::: "memory")

__device__ __forceinline__ void copy_w(uint32_t dst, const __half* __restrict__ src,
                                       int tid) {
    #pragma unroll
    for (int i = tid; i < 576; i += NT)
        asm volatile("cp.async.cg.shared.global [%0], [%1], 16;"
                     :: "r"(dst + 16u * (uint32_t)i), "l"(src + 8 * i) : "memory");
}

__device__ __forceinline__ void gemmF16(uint32_t aB, uint32_t bB, int tt, int cc,
                                        int lane, float acc[4][4]) {
    int ar = tt + (lane & 7) + 8 * ((lane >> 3) & 1), ak = 8 * (lane >> 4);
    int br = cc + (lane & 7) + 8 * (lane >> 4), bk = 8 * ((lane >> 3) & 1);
    uint32_t aA = aB + (uint32_t)((ar * 72 + ak) * 2);
    uint32_t bA0 = bB + (uint32_t)((br * 72 + bk) * 2);
    uint32_t bA1 = bA0 + 16 * 144;
    #pragma unroll
    for (int ks = 0; ks < 4; ks++) {
        uint32_t a0, a1, a2, a3, b0, b1, b2, b3;
        LDSM4(a0, a1, a2, a3, aA + 32 * ks);
        LDSM4(b0, b1, b2, b3, bA0 + 32 * ks);
        MMA16(acc[0], a0, a1, a2, a3, b0, b1);
        MMA16(acc[1], a0, a1, a2, a3, b2, b3);
        LDSM4(b0, b1, b2, b3, bA1 + 32 * ks);
        MMA16(acc[2], a0, a1, a2, a3, b0, b1);
        MMA16(acc[3], a0, a1, a2, a3, b2, b3);
    }
}

// ---------------------------------------------------------------------------
// Merged precursor: blocks [0,512) = pool (one (b,c) image per block, 16
// independent float4 loads per thread for full MLP), [512,525) = weight prep.
// ---------------------------------------------------------------------------
__global__ void __launch_bounds__(256) pre_kernel(
    const float* __restrict__ te,
    const float* __restrict__ qw, const float* __restrict__ kw,
    const float* __restrict__ vw, const float* __restrict__ ow,
    const float* __restrict__ fc1w, const float* __restrict__ fc2w,
    const float* __restrict__ cw,
    const float* __restrict__ ln1w, const float* __restrict__ ln1b,
    const float* __restrict__ ln2w, const float* __restrict__ ln2b,
    const float* __restrict__ qb, const float* __restrict__ fc1b) {
    const int tid = threadIdx.x;
    if (blockIdx.x < 512) {
        // pool: block = (b, c). thread: cols (lane)*4, rows w*4..w*4+3 in each
        // of the 4 ic cells. 16 independent float4 loads -> 4 cell partials.
        __shared__ float sw[4][32];  // [ic][warp*4 + jc]
        const int lane = tid & 31, w = tid >> 5;
        const int c = blockIdx.x & 63, b = blockIdx.x >> 6;
        const float* img = te + ((size_t)(b * 64 + c)) * NPIX;
        float cell[4];
        #pragma unroll
        for (int ic = 0; ic < 4; ic++) {
            const float* src = img + (size_t)(ic * 32 + w * 4) * 128 + lane * 4;
            float4 v0 = *reinterpret_cast<const float4*>(src);
            float4 v1 = *reinterpret_cast<const float4*>(src + 128);
            float4 v2 = *reinterpret_cast<const float4*>(src + 256);
            float4 v3 = *reinterpret_cast<const float4*>(src + 384);
            cell[ic] = (v0.x + v0.y + v0.z + v0.w) + (v1.x + v1.y + v1.z + v1.w) +
                       (v2.x + v2.y + v2.z + v2.w) + (v3.x + v3.y + v3.z + v3.w);
        }
        #pragma unroll
        for (int ic = 0; ic < 4; ic++) {
            float s = cell[ic];
            s += __shfl_xor_sync(~0u, s, 1);
            s += __shfl_xor_sync(~0u, s, 2);
            s += __shfl_xor_sync(~0u, s, 4);
            if ((lane & 7) == 0) sw[ic][w * 4 + (lane >> 3)] = s;
        }
        __syncthreads();
        if (tid < 16) {
            int ic = tid >> 2, jc = tid & 3;
            float tsum = 0.f;
            #pragma unroll
            for (int ww = 0; ww < 8; ww++) tsum += sw[ic][ww * 4 + jc];
            g_te[b * 1024 + c * 16 + ic * 4 + jc] = tsum * (1.0f / 1024.0f);
        }
        return;
    }
    // prep: convert/transpose weights; fold LN affines + QS; parallel bias folds
    const int slot = blockIdx.x - 512;
    __half* dst = g_wt + slot * 4608;
    for (int i = tid; i < 4608; i += 256) {
        int o = i / 72, k = i % 72;
        float v = 0.f;
        if (k < 64) {
            if (slot == 0) v = qw[k * 64 + o] * ln1w[k] * QS;
            else if (slot == 1) v = kw[k * 64 + o];
            else if (slot == 2) v = vw[k * 64 + o];
            else if (slot == 3) v = ow[k * 64 + o];
            else if (slot < 8) v = fc1w[k * 256 + (slot - 4) * 64 + o] * ln2w[k];
            else if (slot < 12) v = fc2w[(slot - 8) * 4096 + k * 64 + o];
            else v = cw[o * 64 + k];
        }
        dst[i] = __float2half(v);
    }
    if (slot == 0) {
        int j = tid >> 2, part = tid & 3;
        float s = 0.f;
        #pragma unroll
        for (int k = 16 * part; k < 16 * part + 16; k++)
            s = fmaf(ln1b[k], qw[k * 64 + j], s);
        s += __shfl_xor_sync(~0u, s, 1);
        s += __shfl_xor_sync(~0u, s, 2);
        if (part == 0) g_qb2[j] = (s + qb[j]) * QS;
    } else if (slot >= 4 && slot < 8) {
        int j = (slot - 4) * 64 + (tid >> 2), part = tid & 3;
        float s = 0.f;
        #pragma unroll
        for (int k = 16 * part; k < 16 * part + 16; k++)
            s = fmaf(ln2b[k], fc1w[k * 256 + j], s);
        s += __shfl_xor_sync(~0u, s, 1);
        s += __shfl_xor_sync(~0u, s, 2);
        if (part == 0) g_fc1b2[j] = s + fc1b[j];
    }
}

// film: 512 threads, 4 partials per output
__global__ void __launch_bounds__(512) film_kernel(
    const float* __restrict__ m1w, const float* __restrict__ m1b,
    const float* __restrict__ m2w, const float* __restrict__ m2b) {
    __shared__ float ste[1024];
    __shared__ float red[512];
    __shared__ float shm[128];
    const int b = blockIdx.x, tid = threadIdx.x;
    const int j = tid & 127, p = tid >> 7;
    for (int i = tid; i < 1024; i += 512) ste[i] = g_te[b * 1024 + i];
    __syncthreads();
    float a = 0.f;
    #pragma unroll 4
    for (int k = 256 * p; k < 256 * p + 256; k++)
        a = fmaf(ste[k], m1w[k * 128 + j], a);
    red[tid] = a;
    __syncthreads();
    if (tid < 128) {
        float acc = red[tid] + red[tid + 128] + red[tid + 256] + red[tid + 384] + m1b[tid];
        shm[tid] = acc > 0.f ? acc : 0.01f * acc;
    }
    __syncthreads();
    float c = 0.f;
    #pragma unroll 4
    for (int k = 32 * p; k < 32 * p + 32; k++)
        c = fmaf(shm[k], m2w[k * 128 + j], c);
    red[tid] = c;
    __syncthreads();
    if (tid < 128)
        g_film[b * 128 + tid] =
            red[tid] + red[tid + 128] + red[tid + 256] + red[tid + 384] + m2b[tid];
}

// half offsets
constexpr int H_H = 0, H_ACT = 9216, H_XQ = 18432, H_KS = 27648, H_VC = 44032;
constexpr int H_F = 52736;
constexpr int SMEM_BYTES = (52736 + 768) * 2;  // 107008

__device__ __forceinline__ void stage_act(__half* dst, const float* __restrict__ g, int tid) {
    #pragma unroll
    for (int i = tid; i < 4096; i += NT) {
        int tok = i & 127, c = (i >> 7) << 1;
        *reinterpret_cast<half2*>(dst + tok * 72 + c) =
            __floats2half2_rn(g[(size_t)c * NPIX + tok], g[(size_t)(c + 1) * NPIX + tok]);
    }
}

__global__ void __launch_bounds__(NT, 2) fused_kernel(
    const float* __restrict__ x, const float* __restrict__ te,
    const float* __restrict__ kb, const float* __restrict__ vb,
    const float* __restrict__ ob, const float* __restrict__ fc2b,
    const float* __restrict__ cb, float* __restrict__ out) {
    extern __shared__ __align__(16) __half sh[];
    float* fm = reinterpret_cast<float*>(sh + H_F);
    const int tid = threadIdx.x;
    const int w = tid >> 5, lane = tid & 31;
    const int g = lane >> 2, t = lane & 3;
    const int tt = 16 * (w & 3), cc = 32 * (w >> 2);
    const int b = blockIdx.x >> 7, row = blockIdx.x & 127;
    const size_t base = (size_t)b * 64 * NPIX + (size_t)row * 128;
    const uint32_t ub = s2u32(sh);
    const int o0 = tt + g, o1 = o0 + 8;

    // A: async weight copies + x/prior staging + film
    copy_w(ub + H_KS * 2, g_wt + 1 * 4608, tid);            // kw
    copy_w(ub + (H_KS + 4608) * 2, g_wt + 2 * 4608, tid);   // vw
    copy_w(ub + H_VC * 2, g_wt + 0 * 4608, tid);            // qw'
    CPCOMMIT;
    stage_act(sh + H_XQ, x + base, tid);
    stage_act(sh + H_H, te + base, tid);
    if (tid < 64) {
        fm[256 + tid] = g_film[b * 128 + tid];
        fm[320 + tid] = g_film[b * 128 + 64 + tid];
    }
    CPWAIT;
    __syncthreads();

    // B: LN1 stats
    {
        int tok = tid >> 2, p = tid & 3;
        const half2* rp = reinterpret_cast<const half2*>(sh + H_H + tok * 72 + p * 16);
        float sum = 0.f, sq = 0.f;
        #pragma unroll
        for (int m = 0; m < 8; m++) {
            float2 v = __half22float2(rp[m]);
            sum += v.x + v.y; sq += v.x * v.x + v.y * v.y;
        }
        sum += __shfl_xor_sync(~0u, sum, 1); sum += __shfl_xor_sync(~0u, sum, 2);
        sq += __shfl_xor_sync(~0u, sq, 1); sq += __shfl_xor_sync(~0u, sq, 2);
        if (p == 0) {
            float mu = sum * (1.f / 64.f);
            fm[tok] = mu;
            fm[128 + tok] = rsqrtf(fmaxf(sq * (1.f / 64.f) - mu * mu, 0.f) + 1e-5f);
        }
    }
    __syncthreads();
    // normalize z only (LN affine folded into qw')
    #pragma unroll
    for (int i = tid; i < 4096; i += NT) {
        int tok = i & 127, c = (i >> 7) << 1;
        float2 v = __half22float2(*reinterpret_cast<half2*>(sh + H_H + tok * 72 + c));
        float mu = fm[tok], rs = fm[128 + tok];
        *reinterpret_cast<half2*>(sh + H_ACT + tok * 72 + c) =
            __floats2half2_rn((v.x - mu) * rs, (v.y - mu) * rs);
    }
    __syncthreads();

    // C1: K,V GEMMs
    float aK[4][4] = {}, aV[4][4] = {};
    gemmF16(ub + H_KS * 2, ub + H_XQ * 2, tt, cc, lane, aK);
    gemmF16(ub + (H_KS + 4608) * 2, ub + H_XQ * 2, tt, cc, lane, aV);
    __syncthreads();
    // zero KS
    #pragma unroll
    for (int i = tid; i < 2048; i += NT)
        reinterpret_cast<uint4*>(sh + H_KS)[i] = make_uint4(0, 0, 0, 0);
    __syncthreads();
    // C2: K epilogue -> K_s; Q GEMM
    {
        int h0 = o0 >> 2, s0 = 4 * (h0 & 1) + (o0 & 3);
        int h1 = o1 >> 2, s1 = 4 * (h1 & 1) + (o1 & 3);
        float kb0 = kb[o0], kb1 = kb[o1];
        #pragma unroll
        for (int j = 0; j < 4; j++) {
            int tok = cc + 8 * j + 2 * t;
            sh[H_KS + h0 * 1024 + tok * 8 + s0] = __float2half(aK[j][0] + kb0);
            sh[H_KS + h0 * 1024 + (tok + 1) * 8 + s0] = __float2half(aK[j][1] + kb0);
            sh[H_KS + h1 * 1024 + tok * 8 + s1] = __float2half(aK[j][2] + kb1);
            sh[H_KS + h1 * 1024 + (tok + 1) * 8 + s1] = __float2half(aK[j][3] + kb1);
        }
    }
    float aQ[4][4] = {};
    gemmF16(ub + H_VC * 2, ub + H_ACT * 2, tt, cc, lane, aQ);
    __syncthreads();
    // C3: V -> VC channel-major; Q (pre-scaled) -> XQ token-major
    {
        float vb0 = vb[o0], vb1 = vb[o1];
        float qb0 = g_qb2[o0], qb1 = g_qb2[o1];
        #pragma unroll
        for (int j = 0; j < 4; j++) {
            int tok = cc + 8 * j + 2 * t;
            *reinterpret_cast<half2*>(sh + H_VC + o0 * 136 + tok) =
                __floats2half2_rn(aV[j][0] + vb0, aV[j][1] + vb0);
            *reinterpret_cast<half2*>(sh + H_VC + o1 * 136 + tok) =
                __floats2half2_rn(aV[j][2] + vb1, aV[j][3] + vb1);
            sh[H_XQ + tok * 72 + o0] = __float2half(aQ[j][0] + qb0);
            sh[H_XQ + (tok + 1) * 72 + o0] = __float2half(aQ[j][1] + qb0);
            sh[H_XQ + tok * 72 + o1] = __float2half(aQ[j][2] + qb1);
            sh[H_XQ + (tok + 1) * 72 + o1] = __float2half(aQ[j][3] + qb1);
        }
    }
    __syncthreads();

    // D: MMA attention — warp = head w; ow copy overlapped with mainloop
    {
        const int h = w, p8 = (h >> 1) * 8;
        uint32_t kb_[16];
        uint32_t ksb = ub + (uint32_t)(H_KS + h * 1024) * 2 + (uint32_t)((lane & 15) * 16);
        #pragma unroll
        for (int jj = 0; jj < 8; jj++) LDSM2(kb_[2 * jj], kb_[2 * jj + 1], ksb + 256 * jj);
        __syncthreads();  // all K_s reads done
        copy_w(ub + H_KS * 2, g_wt + 3 * 4608, tid);  // ow (overlaps loop below)
        CPCOMMIT;
        const uint32_t qbase = ub + (uint32_t)H_XQ * 2 + (uint32_t)(((lane & 15) * 72 + p8) * 2);
        const uint32_t vbase = ub + (uint32_t)(H_VC + (4 * h + (lane & 7)) * 136 +
                                               8 * ((lane >> 3) & 1)) * 2;
        #pragma unroll
        for (int qt = 0; qt < 8; qt++) {
            uint32_t a0, a1;
            LDSM2(a0, a1, qbase + qt * (16 * 144));
            float pv[4] = {0.f, 0.f, 0.f, 0.f};
            half2 lg = __float2half2_rn(0.f), lh = __float2half2_rn(0.f);
            float lfg = 0.f, lfh = 0.f;
            #pragma unroll
            for (int j = 0; j < 8; j++) {
                float c[4] = {0.f, 0.f, 0.f, 0.f}, d[4] = {0.f, 0.f, 0.f, 0.f};
                MMA8(c, a0, a1, kb_[2 * j]);
                MMA8(d, a0, a1, kb_[2 * j + 1]);
                uint32_t e0 = expp(c[0], c[1]), e1 = expp(c[2], c[3]);
                uint32_t e2 = expp(d[0], d[1]), e3 = expp(d[2], d[3]);
                lg = __hadd2(lg, __hadd2(u2h(e0), u2h(e2)));
                lh = __hadd2(lh, __hadd2(u2h(e1), u2h(e3)));
                uint32_t vb0, vb1;
                LDSM2(vb0, vb1, vbase + 32 * j);
                MMA16(pv, e0, e1, e2, e3, vb0, vb1);
                if ((j & 3) == 3) {
                    float2 f = __half22float2(lg); lfg += f.x + f.y;
                    f = __half22float2(lh); lfh += f.x + f.y;
                    lg = __float2half2_rn(0.f); lh = __float2half2_rn(0.f);
                }
            }
            lfg += __shfl_xor_sync(~0u, lfg, 1); lfg += __shfl_xor_sync(~0u, lfg, 2);
            lfh += __shfl_xor_sync(~0u, lfh, 1); lfh += __shfl_xor_sync(~0u, lfh, 2);
            float ig = __fdividef(1.f, lfg), ih = __fdividef(1.f, lfh);
            if (t < 2) {
                int tokg = 16 * qt + g;
                *reinterpret_cast<half2*>(sh + H_ACT + tokg * 72 + 4 * h + 2 * t) =
                    __floats2half2_rn(pv[0] * ig, pv[1] * ig);
                *reinterpret_cast<half2*>(sh + H_ACT + (tokg + 8) * 72 + 4 * h + 2 * t) =
                    __floats2half2_rn(pv[2] * ih, pv[3] * ih);
            }
        }
    }
    CPWAIT;
    __syncthreads();

    // E: O GEMM, h = acc + ob + prior (RMW H)
    {
        float aO[4][4] = {};
        gemmF16(ub + H_KS * 2, ub + H_ACT * 2, tt, cc, lane, aO);
        float b0 = ob[o0], b1 = ob[o1];
        #pragma unroll
        for (int j = 0; j < 4; j++) {
            int tok = cc + 8 * j + 2 * t;
            #pragma unroll
            for (int d = 0; d < 4; d++) {
                int idx = H_H + (tok + (d & 1)) * 72 + ((d < 2) ? o0 : o1);
                sh[idx] = __float2half(aO[j][d] + ((d < 2) ? b0 : b1) + __half2float(sh[idx]));
            }
        }
    }
    __syncthreads();
    // LN2 stats + async copies (fc1'_0, fc2_0, cw)
    {
        int tok = tid >> 2, p = tid & 3;
        const half2* rp = reinterpret_cast<const half2*>(sh + H_H + tok * 72 + p * 16);
        float sum = 0.f, sq = 0.f;
        #pragma unroll
        for (int m = 0; m < 8; m++) {
            float2 v = __half22float2(rp[m]);
            sum += v.x + v.y; sq += v.x * v.x + v.y * v.y;
        }
        sum += __shfl_xor_sync(~0u, sum, 1); sum += __shfl_xor_sync(~0u, sum, 2);
        sq += __shfl_xor_sync(~0u, sq, 1); sq += __shfl_xor_sync(~0u, sq, 2);
        if (p == 0) {
            float mu = sum * (1.f / 64.f);
            fm[tok] = mu;
            fm[128 + tok] = rsqrtf(fmaxf(sq * (1.f / 64.f) - mu * mu, 0.f) + 1e-5f);
        }
    }
    copy_w(ub + (H_KS + 4608) * 2, g_wt + 4 * 4608, tid);
    copy_w(ub + (H_KS + 9216) * 2, g_wt + 8 * 4608, tid);
    copy_w(ub + H_KS * 2, g_wt + 12 * 4608, tid);
    CPCOMMIT;
    __syncthreads();
    // normalize z only (affine folded into fc1w')
    #pragma unroll
    for (int i = tid; i < 4096; i += NT) {
        int tok = i & 127, c = (i >> 7) << 1;
        float2 v = __half22float2(*reinterpret_cast<half2*>(sh + H_H + tok * 72 + c));
        float mu = fm[tok], rs = fm[128 + tok];
        *reinterpret_cast<half2*>(sh + H_ACT + tok * 72 + c) =
            __floats2half2_rn((v.x - mu) * rs, (v.y - mu) * rs);
    }
    CPWAIT;
    __syncthreads();

    // F: FFN (double-buffered)
    float aF2[4][4] = {};
    for (int jb = 0; jb < 4; jb++) {
        float aF1[4][4] = {};
        gemmF16(ub + (H_KS + 4608) * 2, ub + H_ACT * 2, tt, cc, lane, aF1);
        __syncthreads();
        {
            float b0 = g_fc1b2[jb * 64 + o0], b1 = g_fc1b2[jb * 64 + o1];
            #pragma unroll
            for (int j = 0; j < 4; j++) {
                int tok = cc + 8 * j + 2 * t;
                sh[H_XQ + tok * 72 + o0] = __float2half(geluf(aF1[j][0] + b0));
                sh[H_XQ + (tok + 1) * 72 + o0] = __float2half(geluf(aF1[j][1] + b0));
                sh[H_XQ + tok * 72 + o1] = __float2half(geluf(aF1[j][2] + b1));
                sh[H_XQ + (tok + 1) * 72 + o1] = __float2half(geluf(aF1[j][3] + b1));
            }
        }
        if (jb < 3) {
            copy_w(ub + (H_KS + 4608) * 2, g_wt + (5 + jb) * 4608, tid);
            CPCOMMIT;
        }
        CPWAIT;
        __syncthreads();
        gemmF16(ub + (H_KS + 9216) * 2, ub + H_XQ * 2, tt, cc, lane, aF2);
        __syncthreads();
        if (jb < 3) {
            copy_w(ub + (H_KS + 9216) * 2, g_wt + (9 + jb) * 4608, tid);
            CPCOMMIT;
        }
    }
    // G: hfin -> ACT (cw already staged at KS+0)
    {
        float b0 = fc2b[o0], b1 = fc2b[o1];
        #pragma unroll
        for (int j = 0; j < 4; j++) {
            int tok = cc + 8 * j + 2 * t;
            #pragma unroll
            for (int d = 0; d < 4; d++) {
                int tk = tok + (d & 1), o = (d < 2) ? o0 : o1;
                sh[H_ACT + tk * 72 + o] = __float2half(
                    aF2[j][d] + ((d < 2) ? b0 : b1) + __half2float(sh[H_H + tk * 72 + o]));
            }
        }
    }
    CPWAIT;
    __syncthreads();

    // H: conv GEMM + cb + x + FiLM -> out
    {
        float aC[4][4] = {};
        gemmF16(ub + H_KS * 2, ub + H_ACT * 2, tt, cc, lane, aC);
        float cb0 = cb[o0], cb1 = cb[o1];
        float g0 = fm[256 + o0], g1 = fm[256 + o1];
        float bt0 = fm[320 + o0], bt1 = fm[320 + o1];
        #pragma unroll
        for (int j = 0; j < 4; j++) {
            int tok = cc + 8 * j + 2 * t;
            float2 x0 = *reinterpret_cast<const float2*>(&x[base + (size_t)o0 * NPIX + tok]);
            float2 x1 = *reinterpret_cast<const float2*>(&x[base + (size_t)o1 * NPIX + tok]);
            float v; float2 r0, r1;
            v = aC[j][0] + cb0 + x0.x; r0.x = v + g0 * v + bt0;
            v = aC[j][1] + cb0 + x0.y; r0.y = v + g0 * v + bt0;
            v = aC[j][2] + cb1 + x1.x; r1.x = v + g1 * v + bt1;
            v = aC[j][3] + cb1 + x1.y; r1.y = v + g1 * v + bt1;
            *reinterpret_cast<float2*>(&out[base + (size_t)o0 * NPIX + tok]) = r0;
            *reinterpret_cast<float2*>(&out[base + (size_t)o1 * NPIX + tok]) = r1;
        }
    }
}

extern "C" void kernel_launch(void* const* d_in, const int* in_sizes, int n_in,
                              void* d_out, int out_size) {
    const float* x = (const float*)d_in[0];
    const float* te = (const float*)d_in[1];
    cudaFuncSetAttribute(fused_kernel, cudaFuncAttributeMaxDynamicSharedMemorySize,
                         SMEM_BYTES);
    pre_kernel<<<525, 256>>>(te, (const float*)d_in[2], (const float*)d_in[4],
                             (const float*)d_in[6], (const float*)d_in[8],
                             (const float*)d_in[14], (const float*)d_in[16],
                             (const float*)d_in[18], (const float*)d_in[10],
                             (const float*)d_in[11], (const float*)d_in[12],
                             (const float*)d_in[13], (const float*)d_in[3],
                             (const float*)d_in[15]);
    film_kernel<<<8, 512>>>((const float*)d_in[20], (const float*)d_in[21],
                            (const float*)d_in[22], (const float*)d_in[23]);
    fused_kernel<<<1024, NT, SMEM_BYTES>>>(
        x, te, (const float*)d_in[5], (const float*)d_in[7], (const float*)d_in[9],
        (const float*)d_in[17], (const float*)d_in[19], (float*)d_out);
}